// round 6
// baseline (speedup 1.0000x reference)
#include <cuda_runtime.h>
#include <cstdint>

// out[i, :] = weight[b[i], :], out[0, :] = 0.   N=1e6 cells, 32 f32 each.
//
// R6: kernel sits at the LSU-issue floor of the STG path
//     (LDG 4 + LDS 4 + STG.128 12 = 20 cyc per warp-512B).
// Replace STG.128 (12 cyc) with STS.128 (4 cyc) + per-WARP 1D cp.async.bulk
// drain (TMA store, no per-element issue cost). No block barriers (R4's
// mistake) — each warp owns a private double-buffered 2x4KB smem region,
// syncs only with __syncwarp, and lane 0 issues/commits/waits its own
// bulk groups. Fill cost: LDG idx 4 + LDG weight 4 (L1-resident 8KB) +
// STS.128 4 = 12 cyc/group, +~4 cyc/group amortized warp-sync/TMA overhead.

constexpr int BLOCK = 256;
constexpr int WARPS = BLOCK / 32;             // 8
constexpr int TILE_CHUNKS = 256;              // float4 per warp-tile = 4 KB
constexpr int ITERS = TILE_CHUNKS / 32;       // 8 warp-512B groups per tile
constexpr int BUF_BYTES = TILE_CHUNKS * 16;   // 4096
constexpr int SMEM_BYTES = WARPS * 2 * BUF_BYTES;  // 64 KB dynamic

__global__ __launch_bounds__(BLOCK)
void batch_effect_kernel(const int* __restrict__ b,
                         const float4* __restrict__ w,
                         float4* __restrict__ out,
                         unsigned int total_chunks,
                         unsigned int n_tiles)
{
    extern __shared__ float4 smem[];          // [WARPS][2][TILE_CHUNKS]
    const int wid = threadIdx.x >> 5;
    const int lane = threadIdx.x & 31;
    float4* const bufs = smem + wid * 2 * TILE_CHUNKS;

    const unsigned int gw = blockIdx.x * WARPS + wid;   // global warp id
    const unsigned int nw = gridDim.x * WARPS;

    unsigned int iter = 0;
    for (unsigned int tile = gw; tile < n_tiles; tile += nw, iter++) {
        float4* buf = bufs + (iter & 1u) * TILE_CHUNKS;

        // Backpressure: before overwriting this buffer (committed 2 iters
        // ago), allow only the most recent group to still be reading smem.
        if (iter >= 2) {
            if (lane == 0)
                asm volatile("cp.async.bulk.wait_group.read 1;" ::: "memory");
            __syncwarp();
        }

        unsigned int base = tile * TILE_CHUNKS;
        #pragma unroll
        for (int i = 0; i < ITERS; i++) {
            unsigned int t = base + i * 32 + lane;
            int bi = __ldg(&b[t >> 3]);
            float4 v = __ldg(&w[((unsigned)bi << 3) | (t & 7u)]);
            if (t < 8u) v = make_float4(0.f, 0.f, 0.f, 0.f);
            buf[i * 32 + lane] = v;           // STS.128, conflict-free
        }
        __syncwarp();

        if (lane == 0) {
            asm volatile("fence.proxy.async.shared::cta;" ::: "memory");
            asm volatile(
                "cp.async.bulk.global.shared::cta.bulk_group [%0], [%1], %2;"
                :: "l"(out + base),
                   "r"((unsigned)__cvta_generic_to_shared(buf)),
                   "n"(BUF_BYTES)
                : "memory");
            asm volatile("cp.async.bulk.commit_group;" ::: "memory");
        }
    }

    // smem must stay alive until all of this warp's bulk reads complete
    if (lane == 0)
        asm volatile("cp.async.bulk.wait_group.read 0;" ::: "memory");

    // Generic tail (total_chunks not a multiple of TILE_CHUNKS): direct STG.
    for (unsigned int t = n_tiles * TILE_CHUNKS + blockIdx.x * BLOCK + threadIdx.x;
         t < total_chunks; t += gridDim.x * BLOCK) {
        int bi = __ldg(&b[t >> 3]);
        float4 v = __ldg(&w[((unsigned)bi << 3) | (t & 7u)]);
        if (t < 8u) v = make_float4(0.f, 0.f, 0.f, 0.f);
        out[t] = v;
    }
}

extern "C" void kernel_launch(void* const* d_in, const int* in_sizes, int n_in,
                              void* d_out, int out_size)
{
    const int* b = (const int*)d_in[0];          // [N, 1] int32
    const float4* w = (const float4*)d_in[1];    // [64, 32] f32 = 512 float4
    float4* out = (float4*)d_out;                // [N, 32] f32 = N*8 float4

    unsigned int n_cells = (unsigned int)in_sizes[0];
    unsigned int total_chunks = n_cells * 8u;            // 8e6
    unsigned int n_tiles = total_chunks / TILE_CHUNKS;   // full 4KB tiles

    static int smem_set = 0;
    if (!smem_set) {
        cudaFuncSetAttribute(batch_effect_kernel,
                             cudaFuncAttributeMaxDynamicSharedMemorySize,
                             SMEM_BYTES);
        smem_set = 1;
    }

    unsigned int grid = 296;                     // 2 CTAs/SM, persistent-ish
    if (grid > n_tiles / WARPS + 1) grid = n_tiles / WARPS + 1;

    batch_effect_kernel<<<grid, BLOCK, SMEM_BYTES>>>(b, w, out,
                                                     total_chunks, n_tiles);
}

// round 14
// speedup vs baseline: 1.2105x; 1.2105x over previous
#include <cuda_runtime.h>
#include <cstdint>

// out[i, :] = weight[b[i], :], out[0, :] = 0.   N=1e6 cells, 32 f32 each.
//
// R7 (7th resubmit; repeated broker timeouts): direct-STG path is
// LSU-issue-bound (~20 cyc per warp-512B: LDG idx 4 + LDS 4 + STG.128 12).
// Use Blackwell 256-bit global accesses: one thread = one 32B chunk, one
// warp = 1KB contiguous output in a single STG.256. Weight rows via LDG.256
// (8KB table L1-resident). U=4 batched index loads for latency hiding.
// No smem, no barriers.

constexpr int BLOCK = 256;
constexpr int U = 4;

__device__ __forceinline__ void ldg256(const float* p, unsigned r[8]) {
    asm volatile("ld.global.nc.v8.b32 {%0,%1,%2,%3,%4,%5,%6,%7}, [%8];"
                 : "=r"(r[0]), "=r"(r[1]), "=r"(r[2]), "=r"(r[3]),
                   "=r"(r[4]), "=r"(r[5]), "=r"(r[6]), "=r"(r[7])
                 : "l"(p));
}

__device__ __forceinline__ void stg256(float* p, const unsigned r[8]) {
    asm volatile("st.global.v8.b32 [%0], {%1,%2,%3,%4,%5,%6,%7,%8};"
                 :: "l"(p),
                    "r"(r[0]), "r"(r[1]), "r"(r[2]), "r"(r[3]),
                    "r"(r[4]), "r"(r[5]), "r"(r[6]), "r"(r[7])
                 : "memory");
}

__global__ __launch_bounds__(BLOCK)
void batch_effect_kernel(const int* __restrict__ b,
                         const float* __restrict__ w,
                         float* __restrict__ out,
                         unsigned int total32)   // number of 32B chunks = N*4
{
    unsigned int c0 = blockIdx.x * (BLOCK * U) + threadIdx.x;

    if (c0 + (U - 1) * BLOCK < total32) {
        // Full tile: batch the 4 index loads (MLP), then gather+store.
        int bi[U];
        #pragma unroll
        for (int u = 0; u < U; u++) {
            unsigned int c = c0 + u * BLOCK;
            bi[u] = __ldg(&b[c >> 2]);          // cell = c/4
        }
        #pragma unroll
        for (int u = 0; u < U; u++) {
            unsigned int c = c0 + u * BLOCK;
            unsigned r[8];
            ldg256(w + ((unsigned)bi[u] << 5) + ((c & 3u) << 3), r);
            if (c < 4u) {
                #pragma unroll
                for (int k = 0; k < 8; k++) r[k] = 0u;
            }
            stg256(out + (c << 3), r);
        }
    } else {
        // Tail tile
        #pragma unroll
        for (int u = 0; u < U; u++) {
            unsigned int c = c0 + u * BLOCK;
            if (c < total32) {
                int bi = __ldg(&b[c >> 2]);
                unsigned r[8];
                ldg256(w + ((unsigned)bi << 5) + ((c & 3u) << 3), r);
                if (c < 4u) {
                    #pragma unroll
                    for (int k = 0; k < 8; k++) r[k] = 0u;
                }
                stg256(out + (c << 3), r);
            }
        }
    }
}

extern "C" void kernel_launch(void* const* d_in, const int* in_sizes, int n_in,
                              void* d_out, int out_size)
{
    const int* b = (const int*)d_in[0];          // [N, 1] int32
    const float* w = (const float*)d_in[1];      // [64, 32] f32
    float* out = (float*)d_out;                  // [N, 32] f32

    unsigned int n_cells = (unsigned int)in_sizes[0];
    unsigned int total32 = n_cells * 4u;         // 32B chunks, 4e6
    unsigned int per_block = BLOCK * U;          // 1024 chunks per CTA
    unsigned int grid = (total32 + per_block - 1) / per_block;

    batch_effect_kernel<<<grid, BLOCK>>>(b, w, out, total32);
}

// round 16
// speedup vs baseline: 1.2120x; 1.0013x over previous
#include <cuda_runtime.h>
#include <cstdint>

// out[i, :] = weight[b[i], :], out[0, :] = 0.   N=1e6 cells, 32 f32 each.
//
// R15 (resubmit; broker timeout): kernel is at a chip memory ceiling
// (LTS ~6300 B/cyc; 128MB of stores = ~6.2TB/s through L2), proven by
// STG.256 halving instruction count (issue 10.6%->8.3%) with zero time
// delta. Last lever: phase-separate the DRAM index reads from the store
// stream. Each CTA stages its 256 cell indices into smem in one coalesced
// burst, then runs a pure gather(L1-hit weight) + STG.256 store stream.

constexpr int BLOCK = 256;
constexpr int U = 4;
constexpr int CELLS_PER_CTA = BLOCK * U / 4;    // 256 cells (1024 chunks)

__device__ __forceinline__ void ldg256(const float* p, unsigned r[8]) {
    asm volatile("ld.global.nc.v8.b32 {%0,%1,%2,%3,%4,%5,%6,%7}, [%8];"
                 : "=r"(r[0]), "=r"(r[1]), "=r"(r[2]), "=r"(r[3]),
                   "=r"(r[4]), "=r"(r[5]), "=r"(r[6]), "=r"(r[7])
                 : "l"(p));
}

__device__ __forceinline__ void stg256(float* p, const unsigned r[8]) {
    asm volatile("st.global.v8.b32 [%0], {%1,%2,%3,%4,%5,%6,%7,%8};"
                 :: "l"(p),
                    "r"(r[0]), "r"(r[1]), "r"(r[2]), "r"(r[3]),
                    "r"(r[4]), "r"(r[5]), "r"(r[6]), "r"(r[7])
                 : "memory");
}

__global__ __launch_bounds__(BLOCK)
void batch_effect_kernel(const int* __restrict__ b,
                         const float* __restrict__ w,
                         float* __restrict__ out,
                         unsigned int n_cells,
                         unsigned int total32)   // 32B chunks = N*4
{
    __shared__ int sIdx[CELLS_PER_CTA];

    const unsigned int cell_base = blockIdx.x * CELLS_PER_CTA;

    // Phase 1: coalesced index stage (one 1KB burst per CTA)
    {
        unsigned int cell = cell_base + threadIdx.x;   // BLOCK == CELLS_PER_CTA
        sIdx[threadIdx.x] = (cell < n_cells) ? __ldg(&b[cell]) : 0;
    }
    __syncthreads();

    // Phase 2: pure store stream. chunk c -> cell c>>2, quarter c&3.
    unsigned int c0 = blockIdx.x * (BLOCK * U) + threadIdx.x;

    if (c0 + (U - 1) * BLOCK < total32) {
        #pragma unroll
        for (int u = 0; u < U; u++) {
            unsigned int c = c0 + u * BLOCK;
            int bi = sIdx[(c >> 2) - cell_base];
            unsigned r[8];
            ldg256(w + ((unsigned)bi << 5) + ((c & 3u) << 3), r);
            if (c < 4u) {
                #pragma unroll
                for (int k = 0; k < 8; k++) r[k] = 0u;
            }
            stg256(out + (c << 3), r);
        }
    } else {
        #pragma unroll
        for (int u = 0; u < U; u++) {
            unsigned int c = c0 + u * BLOCK;
            if (c < total32) {
                int bi = sIdx[(c >> 2) - cell_base];
                unsigned r[8];
                ldg256(w + ((unsigned)bi << 5) + ((c & 3u) << 3), r);
                if (c < 4u) {
                    #pragma unroll
                    for (int k = 0; k < 8; k++) r[k] = 0u;
                }
                stg256(out + (c << 3), r);
            }
        }
    }
}

extern "C" void kernel_launch(void* const* d_in, const int* in_sizes, int n_in,
                              void* d_out, int out_size)
{
    const int* b = (const int*)d_in[0];          // [N, 1] int32
    const float* w = (const float*)d_in[1];      // [64, 32] f32
    float* out = (float*)d_out;                  // [N, 32] f32

    unsigned int n_cells = (unsigned int)in_sizes[0];
    unsigned int total32 = n_cells * 4u;         // 4e6
    unsigned int per_block = BLOCK * U;          // 1024 chunks per CTA
    unsigned int grid = (total32 + per_block - 1) / per_block;

    batch_effect_kernel<<<grid, BLOCK>>>(b, w, out, n_cells, total32);
}